// round 3
// baseline (speedup 1.0000x reference)
#include <cuda_runtime.h>
#include <math.h>

#define N_ROWS 8192
#define T_COLS 256

// Scratch (allocation-free __device__ globals; zero-initialized at module load,
// and every execution restores them to zero => graph-replay safe)
__device__ float  g_H[T_COLS * T_COLS];        // H[d][t] = sum over rows i (ev=1, dur=d, lab=t) of exp(-2*A_i)
__device__ float  g_R[2 * T_COLS * T_COLS];    // R[2d+e][t]: e=0 -> sum_{d'<d} H, e=1 -> sum_{d'<=d} H
__device__ float  g_nll[N_ROWS];               // per-row NLL contribution
__device__ float2 g_part[N_ROWS / 8];          // per-block partials {nll, rank}
__device__ unsigned int g_tickets;

__device__ __forceinline__ float warp_max(float v) {
    #pragma unroll
    for (int o = 16; o > 0; o >>= 1)
        v = fmaxf(v, __shfl_xor_sync(0xffffffffu, v, o));
    return v;
}

// ---------------------------------------------------------------------------
// Pass A: per-row softmax scan -> nll_i; scatter ev_i * exp(-2*cdf_i[lab_i])
// into H[dur_i][lab_i] (one atomic per row).
// ---------------------------------------------------------------------------
__global__ void __launch_bounds__(256) passA_kernel(
    const float* __restrict__ hz,
    const int*   __restrict__ dur,
    const int*   __restrict__ ev,
    const int*   __restrict__ lab)
{
    const int row  = (blockIdx.x * blockDim.x + threadIdx.x) >> 5;
    const int lane = threadIdx.x & 31;

    const float4* rp = reinterpret_cast<const float4*>(hz + (size_t)row * T_COLS);
    float4 a = rp[lane * 2];
    float4 b = rp[lane * 2 + 1];
    float v[8] = {a.x, a.y, a.z, a.w, b.x, b.y, b.z, b.w};

    float m = v[0];
    #pragma unroll
    for (int k = 1; k < 8; k++) m = fmaxf(m, v[k]);
    const float gamma = fmaxf(warp_max(m), 0.0f);   // pad column phi=0

    float e[8];
    float local = 0.0f;
    #pragma unroll
    for (int k = 0; k < 8; k++) { e[k] = __expf(v[k] - gamma); local += e[k]; }

    float incl = local;
    #pragma unroll
    for (int o = 1; o < 32; o <<= 1) {
        float t = __shfl_up_sync(0xffffffffu, incl, o);
        if (lane >= o) incl += t;
    }
    const float total = __shfl_sync(0xffffffffu, incl, 31);
    const float offs  = incl - local;

    const int L = lab[row];
    // prefix up to local index (L&7) within owning lane
    const int kk = L & 7;
    float run = offs, cum_sel = 0.0f, phi_sel = v[0];
    #pragma unroll
    for (int k = 0; k < 8; k++) {
        run += e[k];
        if (k == kk) { cum_sel = run; phi_sel = v[k]; }
    }
    const float cum_at = __shfl_sync(0xffffffffu, cum_sel, L >> 3);
    const float phi_at = __shfl_sync(0xffffffffu, phi_sel, L >> 3);

    if (lane == 0) {
        const float EPS = 1e-7f;
        const float sum_ = total + __expf(-gamma);
        const int   evv  = ev[row];
        const float evf  = (evv != 0) ? 1.0f : 0.0f;
        const float part1 = (phi_at - gamma) * evf;
        const float part2 = -logf(fmaxf(sum_, 0.0f) + EPS);
        const float part3 = logf(fmaxf(sum_ - cum_at, 0.0f) + EPS) * (1.0f - evf);
        g_nll[row] = -(part1 + part2 + part3);
        if (evv != 0) {
            const float A = cum_at / sum_;                 // cdf[i, lab_i]
            atomicAdd(&g_H[dur[row] * T_COLS + L], __expf(-2.0f * A));
        }
    }
}

// ---------------------------------------------------------------------------
// Pass B: prefix over d:  R[2d][t] = sum_{d'<d} H[d'][t]
//                         R[2d+1][t] = sum_{d'<=d} H[d'][t]
// Re-zeroes H for the next replay. Threads = columns t (coalesced).
// ---------------------------------------------------------------------------
__global__ void __launch_bounds__(32) passB_kernel() {
    const int t = blockIdx.x * 32 + threadIdx.x;
    float run = 0.0f;
    #pragma unroll 4
    for (int d = 0; d < T_COLS; d++) {
        const float h = g_H[d * T_COLS + t];
        g_R[(2 * d)     * T_COLS + t] = run;
        run += h;
        g_R[(2 * d + 1) * T_COLS + t] = run;
        g_H[d * T_COLS + t] = 0.0f;
    }
}

// ---------------------------------------------------------------------------
// Pass C: per-row recompute softmax scan (hazards are L2-hot), dot with the
// gathered R row (contiguous, L2-hot), reduce nll + rank, write scalar.
// ---------------------------------------------------------------------------
__global__ void __launch_bounds__(256) passC_kernel(
    const float* __restrict__ hz,
    const int*   __restrict__ dur,
    const int*   __restrict__ ev,
    float* __restrict__ out)
{
    __shared__ float2 s[8];
    const int row  = (blockIdx.x * blockDim.x + threadIdx.x) >> 5;
    const int lane = threadIdx.x & 31;
    const int warp = threadIdx.x >> 5;

    const float4* rp = reinterpret_cast<const float4*>(hz + (size_t)row * T_COLS);
    float4 a = rp[lane * 2];
    float4 b = rp[lane * 2 + 1];
    float v[8] = {a.x, a.y, a.z, a.w, b.x, b.y, b.z, b.w};

    float m = v[0];
    #pragma unroll
    for (int k = 1; k < 8; k++) m = fmaxf(m, v[k]);
    const float gamma = fmaxf(warp_max(m), 0.0f);

    float e[8];
    float local = 0.0f;
    #pragma unroll
    for (int k = 0; k < 8; k++) { e[k] = __expf(v[k] - gamma); local += e[k]; }

    float incl = local;
    #pragma unroll
    for (int o = 1; o < 32; o <<= 1) {
        float t = __shfl_up_sync(0xffffffffu, incl, o);
        if (lane >= o) incl += t;
    }
    const float total = __shfl_sync(0xffffffffu, incl, 31);
    float run = incl - local;

    const float sum_ = total + __expf(-gamma);
    const float s2   = 2.0f / sum_;                 // exp(cdf/sigma) = exp(2*cdf)

    const int kj = 2 * dur[row] + ((ev[row] == 0) ? 1 : 0);
    const float4* Rp = reinterpret_cast<const float4*>(g_R + (size_t)kj * T_COLS + lane * 8);
    float4 r0 = Rp[0], r1 = Rp[1];
    float rr[8] = {r0.x, r0.y, r0.z, r0.w, r1.x, r1.y, r1.z, r1.w};

    float dot = 0.0f;
    #pragma unroll
    for (int k = 0; k < 8; k++) {
        run += e[k];
        dot += rr[k] * __expf(run * s2);
    }

    // warp reduce rank; lane0 adds nll
    #pragma unroll
    for (int o = 16; o > 0; o >>= 1)
        dot += __shfl_xor_sync(0xffffffffu, dot, o);

    if (lane == 0) s[warp] = make_float2(g_nll[row], dot);
    __syncthreads();

    if (threadIdx.x < 8) {
        float2 p = s[threadIdx.x];
        #pragma unroll
        for (int o = 4; o > 0; o >>= 1) {
            p.x += __shfl_xor_sync(0xffu, p.x, o);
            p.y += __shfl_xor_sync(0xffu, p.y, o);
        }
        if (threadIdx.x == 0) {
            g_part[blockIdx.x] = p;
            __threadfence();
            unsigned int tk = atomicAdd(&g_tickets, 1u);
            if (tk == gridDim.x - 1) {
                // last block: final reduce of all partials
                float nll_sum = 0.0f, rank_sum = 0.0f;
                for (int i = 0; i < (int)gridDim.x; i++) {
                    float2 q = g_part[i];
                    nll_sum += q.x; rank_sum += q.y;
                }
                const float ALPHA = 0.5f;
                out[0] = ALPHA * (nll_sum / (float)N_ROWS)
                       + (1.0f - ALPHA) * (rank_sum / ((float)N_ROWS * (float)N_ROWS));
                g_tickets = 0u;   // restore invariant for next replay
            }
        }
    }
}

extern "C" void kernel_launch(void* const* d_in, const int* in_sizes, int n_in,
                              void* d_out, int out_size)
{
    const float* hz  = (const float*)d_in[0];
    const int*   dur = (const int*)  d_in[1];
    const int*   ev  = (const int*)  d_in[2];
    const int*   lab = (const int*)  d_in[3];
    float* out = (float*)d_out;

    passA_kernel<<<N_ROWS / 8, 256>>>(hz, dur, ev, lab);
    passB_kernel<<<T_COLS / 32, 32>>>();
    passC_kernel<<<N_ROWS / 8, 256>>>(hz, dur, ev, out);
}

// round 4
// speedup vs baseline: 6.1158x; 6.1158x over previous
#include <cuda_runtime.h>
#include <math.h>

#define N_ROWS 8192
#define T_COLS 256

// Scratch (allocation-free __device__ globals; zero at module load, and every
// execution restores invariants => graph-replay safe)
__device__ float g_H[T_COLS * T_COLS];       // H[lab][dur] = sum over rows i (ev=1) of exp(-2*A_i)
__device__ float g_R[2 * T_COLS * T_COLS];   // R[2d+e][t]: e=0 -> sum_{d'<d} H[t][d'], e=1 -> sum_{d'<=d}
__device__ float g_acc[2];                   // {nll_sum, rank_sum}
__device__ unsigned int g_tickets;

__device__ __forceinline__ float warp_max(float v) {
    #pragma unroll
    for (int o = 16; o > 0; o >>= 1)
        v = fmaxf(v, __shfl_xor_sync(0xffffffffu, v, o));
    return v;
}
__device__ __forceinline__ float warp_sum(float v) {
    #pragma unroll
    for (int o = 16; o > 0; o >>= 1)
        v += __shfl_xor_sync(0xffffffffu, v, o);
    return v;
}

// ---------------------------------------------------------------------------
// Pass A: per-row masked reduce -> scatter ev_i * exp(-2*cdf_i[lab_i]) into
// H[lab_i][dur_i] (one atomic per row). No scan needed: cum_at is a reduce.
// ---------------------------------------------------------------------------
__global__ void __launch_bounds__(256) passA_kernel(
    const float* __restrict__ hz,
    const int*   __restrict__ dur,
    const int*   __restrict__ ev,
    const int*   __restrict__ lab)
{
    const int row  = (blockIdx.x * blockDim.x + threadIdx.x) >> 5;
    const int lane = threadIdx.x & 31;

    if (ev[row] == 0) return;   // only ev=1 rows contribute to H

    const float4* rp = reinterpret_cast<const float4*>(hz + (size_t)row * T_COLS);
    float4 a = rp[lane * 2];
    float4 b = rp[lane * 2 + 1];
    float v[8] = {a.x, a.y, a.z, a.w, b.x, b.y, b.z, b.w};

    float m = v[0];
    #pragma unroll
    for (int k = 1; k < 8; k++) m = fmaxf(m, v[k]);
    const float gamma = fmaxf(warp_max(m), 0.0f);   // pad column phi=0

    const int L = lab[row];
    float tot = 0.0f, csum = 0.0f;
    #pragma unroll
    for (int k = 0; k < 8; k++) {
        const float e = __expf(v[k] - gamma);
        tot += e;
        if (lane * 8 + k <= L) csum += e;
    }
    tot  = warp_sum(tot);
    csum = warp_sum(csum);

    if (lane == 0) {
        const float sum_ = tot + __expf(-gamma);
        const float A    = csum / sum_;              // cdf[i, lab_i]
        atomicAdd(&g_H[L * T_COLS + dur[row]], __expf(-2.0f * A));
    }
}

// ---------------------------------------------------------------------------
// Pass B: one warp per column t (=lab). Contiguous float4 loads over d,
// warp prefix scan, write R[2d+e][t] (scattered stores, cheap). Re-zero H.
// 32 blocks x 256 threads = 256 warps.
// ---------------------------------------------------------------------------
__global__ void __launch_bounds__(256) passB_kernel() {
    const int t    = (blockIdx.x * blockDim.x + threadIdx.x) >> 5;
    const int lane = threadIdx.x & 31;

    float4* hp = reinterpret_cast<float4*>(&g_H[t * T_COLS + lane * 8]);
    float4 h0 = hp[0], h1 = hp[1];
    float h[8] = {h0.x, h0.y, h0.z, h0.w, h1.x, h1.y, h1.z, h1.w};

    float local = 0.0f;
    #pragma unroll
    for (int k = 0; k < 8; k++) local += h[k];

    // exclusive prefix over lanes
    float incl = local;
    #pragma unroll
    for (int o = 1; o < 32; o <<= 1) {
        float u = __shfl_up_sync(0xffffffffu, incl, o);
        if (lane >= o) incl += u;
    }
    float run = incl - local;   // sum over lanes < lane

    #pragma unroll
    for (int k = 0; k < 8; k++) {
        const int d = lane * 8 + k;
        g_R[(2 * d)     * T_COLS + t] = run;   // sum_{d'<d}
        run += h[k];
        g_R[(2 * d + 1) * T_COLS + t] = run;   // sum_{d'<=d}
    }

    // re-zero H for next replay
    hp[0] = make_float4(0.f, 0.f, 0.f, 0.f);
    hp[1] = make_float4(0.f, 0.f, 0.f, 0.f);
}

// ---------------------------------------------------------------------------
// Pass C: per-row softmax scan (hazards L2-hot), nll + dot with coalesced
// R[kj][.] row, block-reduce, atomic accumulate; last ticket writes scalar.
// ---------------------------------------------------------------------------
__global__ void __launch_bounds__(256) passC_kernel(
    const float* __restrict__ hz,
    const int*   __restrict__ dur,
    const int*   __restrict__ ev,
    const int*   __restrict__ lab,
    float* __restrict__ out)
{
    __shared__ float2 s[8];
    const int row  = (blockIdx.x * blockDim.x + threadIdx.x) >> 5;
    const int lane = threadIdx.x & 31;
    const int warp = threadIdx.x >> 5;

    const float4* rp = reinterpret_cast<const float4*>(hz + (size_t)row * T_COLS);
    float4 a = rp[lane * 2];
    float4 b = rp[lane * 2 + 1];
    float v[8] = {a.x, a.y, a.z, a.w, b.x, b.y, b.z, b.w};

    float m = v[0];
    #pragma unroll
    for (int k = 1; k < 8; k++) m = fmaxf(m, v[k]);
    const float gamma = fmaxf(warp_max(m), 0.0f);

    float e[8];
    float local = 0.0f;
    #pragma unroll
    for (int k = 0; k < 8; k++) { e[k] = __expf(v[k] - gamma); local += e[k]; }

    float incl = local;
    #pragma unroll
    for (int o = 1; o < 32; o <<= 1) {
        float u = __shfl_up_sync(0xffffffffu, incl, o);
        if (lane >= o) incl += u;
    }
    const float total = __shfl_sync(0xffffffffu, incl, 31);
    float run = incl - local;

    const float sum_ = total + __expf(-gamma);
    const float s2   = 2.0f / sum_;                 // exp(cdf/sigma) = exp(2*cdf)

    const int evv = ev[row];
    const int L   = lab[row];
    const int kj  = 2 * dur[row] + ((evv == 0) ? 1 : 0);

    const float4* Rp = reinterpret_cast<const float4*>(g_R + (size_t)kj * T_COLS + lane * 8);
    float4 r0 = Rp[0], r1 = Rp[1];
    float rr[8] = {r0.x, r0.y, r0.z, r0.w, r1.x, r1.y, r1.z, r1.w};

    const int kk = L & 7;
    float cum_sel = 0.0f, phi_sel = v[0];
    float dot = 0.0f;
    #pragma unroll
    for (int k = 0; k < 8; k++) {
        run += e[k];
        if (k == kk) { cum_sel = run; phi_sel = v[k]; }
        dot += rr[k] * __expf(run * s2);
    }
    const float cum_at = __shfl_sync(0xffffffffu, cum_sel, L >> 3);
    const float phi_at = __shfl_sync(0xffffffffu, phi_sel, L >> 3);

    dot = warp_sum(dot);

    if (lane == 0) {
        const float EPS = 1e-7f;
        const float evf = (evv != 0) ? 1.0f : 0.0f;
        const float part1 = (phi_at - gamma) * evf;
        const float part2 = -logf(fmaxf(sum_, 0.0f) + EPS);
        const float part3 = logf(fmaxf(sum_ - cum_at, 0.0f) + EPS) * (1.0f - evf);
        s[warp] = make_float2(-(part1 + part2 + part3), dot);
    }
    __syncthreads();

    if (threadIdx.x < 8) {
        float2 p = s[threadIdx.x];
        #pragma unroll
        for (int o = 4; o > 0; o >>= 1) {
            p.x += __shfl_xor_sync(0xffu, p.x, o);
            p.y += __shfl_xor_sync(0xffu, p.y, o);
        }
        if (threadIdx.x == 0) {
            atomicAdd(&g_acc[0], p.x);
            atomicAdd(&g_acc[1], p.y);
            __threadfence();
            unsigned int tk = atomicAdd(&g_tickets, 1u);
            if (tk == gridDim.x - 1) {
                // atomicExch: coherent read of final sums + reset for next replay
                const float nll_sum  = atomicExch(&g_acc[0], 0.0f);
                const float rank_sum = atomicExch(&g_acc[1], 0.0f);
                const float ALPHA = 0.5f;
                out[0] = ALPHA * (nll_sum / (float)N_ROWS)
                       + (1.0f - ALPHA) * (rank_sum / ((float)N_ROWS * (float)N_ROWS));
                atomicExch(&g_tickets, 0u);
            }
        }
    }
}

extern "C" void kernel_launch(void* const* d_in, const int* in_sizes, int n_in,
                              void* d_out, int out_size)
{
    const float* hz  = (const float*)d_in[0];
    const int*   dur = (const int*)  d_in[1];
    const int*   ev  = (const int*)  d_in[2];
    const int*   lab = (const int*)  d_in[3];
    float* out = (float*)d_out;

    passA_kernel<<<N_ROWS / 8, 256>>>(hz, dur, ev, lab);
    passB_kernel<<<32, 256>>>();
    passC_kernel<<<N_ROWS / 8, 256>>>(hz, dur, ev, lab, out);
}